// round 2
// baseline (speedup 1.0000x reference)
#include <cuda_runtime.h>
#include <math.h>
#include <stdint.h>

#define NTOK 8192
#define DIM  1024
#define VD   32
#define KCB  4096

// ---------------- device scratch (no allocations allowed) ----------------
__device__ float g_embn[KCB * VD];   // normalized codebook [k][v]
__device__ float g_hp[NTOK * VD];    // normalized projected tokens [t][v]
__device__ float g_hvq[NTOK * VD];   // soft-quantized tokens [t][v]
__device__ int   g_code[NTOK];

// ---------------- warp reduce helpers ----------------
__device__ __forceinline__ float warpSum(float v) {
#pragma unroll
    for (int o = 16; o; o >>= 1) v += __shfl_xor_sync(0xffffffffu, v, o);
    return v;
}
__device__ __forceinline__ float warpMax(float v) {
#pragma unroll
    for (int o = 16; o; o >>= 1) v = fmaxf(v, __shfl_xor_sync(0xffffffffu, v, o));
    return v;
}

// ---------------- Kernel A: normalize codebook rows ----------------
// grid 512 x block 256: one warp per codebook row (4096 rows)
__global__ void k_embnorm(const float* __restrict__ emb) {
    int row  = blockIdx.x * 8 + (threadIdx.x >> 5);
    int lane = threadIdx.x & 31;
    float x  = emb[row * VD + lane];
    float ss = warpSum(x * x);
    g_embn[row * VD + lane] = x * rsqrtf(ss);
}

// ---------------- Kernel B: hp = normalize(h @ Wp^T + bp) ----------------
// grid 256 x block 256 (8 warps). Block handles 32 tokens.
// lane = token, warp owns 4 output dims v. D tiled in chunks of 128 through smem.
__global__ void k_proj(const float* __restrict__ h,
                       const float* __restrict__ Wp,
                       const float* __restrict__ bp) {
    __shared__ __align__(16) float wp_s[32][128];  // [v][d'] broadcast reads
    __shared__ __align__(16) float h_s[32][132];   // [t][d'] lane-varying float4 reads (132/4=33 odd -> conflict free)
    __shared__ __align__(16) float hpbuf[32][33];

    int tid = threadIdx.x, warp = tid >> 5, lane = tid & 31;
    int t0 = blockIdx.x * 32;
    int v0 = warp * 4;
    float acc0 = 0.f, acc1 = 0.f, acc2 = 0.f, acc3 = 0.f;

    for (int c = 0; c < 8; c++) {
        __syncthreads();
#pragma unroll
        for (int i = tid; i < 4096; i += 256) {
            int v = i >> 7, d = i & 127;
            wp_s[v][d] = Wp[v * DIM + c * 128 + d];
        }
#pragma unroll
        for (int i = tid; i < 4096; i += 256) {
            int t = i >> 7, d = i & 127;
            h_s[t][d] = h[(size_t)(t0 + t) * DIM + c * 128 + d];
        }
        __syncthreads();
#pragma unroll 4
        for (int dq = 0; dq < 128; dq += 4) {
            float4 hv = *(const float4*)&h_s[lane][dq];
            float4 w0 = *(const float4*)&wp_s[v0 + 0][dq];
            float4 w1 = *(const float4*)&wp_s[v0 + 1][dq];
            float4 w2 = *(const float4*)&wp_s[v0 + 2][dq];
            float4 w3 = *(const float4*)&wp_s[v0 + 3][dq];
            acc0 += hv.x * w0.x + hv.y * w0.y + hv.z * w0.z + hv.w * w0.w;
            acc1 += hv.x * w1.x + hv.y * w1.y + hv.z * w1.z + hv.w * w1.w;
            acc2 += hv.x * w2.x + hv.y * w2.y + hv.z * w2.z + hv.w * w2.w;
            acc3 += hv.x * w3.x + hv.y * w3.y + hv.z * w3.z + hv.w * w3.w;
        }
    }
    __syncthreads();
    hpbuf[lane][v0 + 0] = acc0 + bp[v0 + 0];
    hpbuf[lane][v0 + 1] = acc1 + bp[v0 + 1];
    hpbuf[lane][v0 + 2] = acc2 + bp[v0 + 2];
    hpbuf[lane][v0 + 3] = acc3 + bp[v0 + 3];
    __syncthreads();
    // normalize: warp handles 4 tokens, lane = v
#pragma unroll
    for (int q = 0; q < 4; q++) {
        int t = warp * 4 + q;
        float x = hpbuf[t][lane];
        float ss = warpSum(x * x);
        g_hp[(size_t)(t0 + t) * VD + lane] = x * rsqrtf(ss);
    }
}

// ---------------- Kernel C: VQ core (scores + online softmax + weighted sum + argmax) --
// grid 512 x block 128 (4 warps). Block handles 16 tokens, each warp 4 tokens.
// K tiled in chunks of 64 codes.
__global__ void k_vq(const float* __restrict__ attn_mask) {
    __shared__ __align__(16) float e_s[64][36];  // [k'][v]: score pass; lane=k' rows (36/4=9 odd, conflict free f4)
    __shared__ __align__(16) float e_t[32][68];  // [v][k']: accum pass; lane=v rows (68/4=17 odd, conflict free f4)
    __shared__ __align__(16) float p_s[16][68];  // probs [t_local][k'], broadcast f4 reads
    __shared__ __align__(16) float hp_s[16][36]; // [t_local][v], broadcast f4 reads

    int tid = threadIdx.x, warp = tid >> 5, lane = tid & 31;
    int t0 = blockIdx.x * 16;
    int tl = warp * 4;  // this warp's local token base

    for (int i = tid; i < 16 * 32; i += 128) {
        int t = i >> 5, v = i & 31;
        hp_s[t][v] = g_hp[(size_t)(t0 + t) * VD + v];
    }

    float m[4]  = {-INFINITY, -INFINITY, -INFINITY, -INFINITY};
    float Z[4]  = {0.f, 0.f, 0.f, 0.f};
    float y[4]  = {0.f, 0.f, 0.f, 0.f};   // lane = v component
    float bv[4] = {-INFINITY, -INFINITY, -INFINITY, -INFINITY};
    int   bk[4] = {0, 0, 0, 0};

    for (int c = 0; c < 64; c++) {
        __syncthreads();
        for (int i = tid; i < 2048; i += 128) {
            int k = i >> 5, v = i & 31;
            float e = g_embn[(size_t)(c * 64 + k) * VD + v];
            e_s[k][v] = e;
            e_t[v][k] = e;
        }
        __syncthreads();

        // ---- score pass: lane owns codes k' = lane and lane+32 ----
        float s0[4] = {0.f, 0.f, 0.f, 0.f};
        float s1[4] = {0.f, 0.f, 0.f, 0.f};
#pragma unroll
        for (int vq = 0; vq < 32; vq += 4) {
            float4 e0 = *(const float4*)&e_s[lane][vq];
            float4 e1 = *(const float4*)&e_s[lane + 32][vq];
#pragma unroll
            for (int q = 0; q < 4; q++) {
                float4 hq = *(const float4*)&hp_s[tl + q][vq];
                s0[q] += hq.x * e0.x + hq.y * e0.y + hq.z * e0.z + hq.w * e0.w;
                s1[q] += hq.x * e1.x + hq.y * e1.y + hq.z * e1.z + hq.w * e1.w;
            }
        }

        // ---- online softmax update + probs to smem ----
        float corr[4];
#pragma unroll
        for (int q = 0; q < 4; q++) {
            float l0 = 2.0f * s0[q], l1 = 2.0f * s1[q];
            int k0 = c * 64 + lane, k1 = k0 + 32;
            if (l0 > bv[q]) { bv[q] = l0; bk[q] = k0; }
            if (l1 > bv[q]) { bv[q] = l1; bk[q] = k1; }
            float mc = warpMax(fmaxf(l0, l1));
            float nm = fmaxf(m[q], mc);
            corr[q] = __expf(m[q] - nm);     // exp(-inf)=0 on first chunk
            float p0 = __expf(l0 - nm);
            float p1 = __expf(l1 - nm);
            p_s[tl + q][lane]      = p0;
            p_s[tl + q][lane + 32] = p1;
            Z[q] = Z[q] * corr[q] + warpSum(p0 + p1);
            m[q] = nm;
        }

        // ---- accumulate pass: lane = v (same warp wrote p_s, no sync needed) ----
#pragma unroll
        for (int q = 0; q < 4; q++) y[q] *= corr[q];
#pragma unroll
        for (int kq = 0; kq < 64; kq += 4) {
            float4 e4 = *(const float4*)&e_t[lane][kq];
#pragma unroll
            for (int q = 0; q < 4; q++) {
                float4 p4 = *(const float4*)&p_s[tl + q][kq];
                y[q] += e4.x * p4.x + e4.y * p4.y + e4.z * p4.z + e4.w * p4.w;
            }
        }
    }

    // ---- finalize: normalize by Z, mask, argmax reduce ----
#pragma unroll
    for (int q = 0; q < 4; q++) {
        int tok = t0 + tl + q;
        float mk = attn_mask[tok];
        float val = y[q] / Z[q];
        if (mk != 1.0f) val = 0.0f;
        g_hvq[(size_t)tok * VD + lane] = val;

        float b = bv[q];
        int kk = bk[q];
#pragma unroll
        for (int o = 16; o; o >>= 1) {
            float ob = __shfl_xor_sync(0xffffffffu, b, o);
            int   ok = __shfl_xor_sync(0xffffffffu, kk, o);
            if (ob > b || (ob == b && ok < kk)) { b = ob; kk = ok; }
        }
        if (lane == 0) g_code[tok] = (mk != 1.0f) ? 0 : kk;
    }
}

// ---------------- Kernel D: quantized = g_hvq @ Wpi^T + bpi ----------------
// grid 256 x block 256 (8 warps). Block: 32 tokens; warp: 4 tokens; lane = output dim d.
__global__ void k_out(const float* __restrict__ Wpi,
                      const float* __restrict__ bpi,
                      float* __restrict__ out) {
    __shared__ __align__(16) float wpi_s[128][36];  // [d'][v] lane-varying f4 (36/4=9 odd)
    __shared__ __align__(16) float hvq_s[32][32];   // broadcast f4 reads

    int tid = threadIdx.x, warp = tid >> 5, lane = tid & 31;
    int t0 = blockIdx.x * 32;
    int tl = warp * 4;

    for (int i = tid; i < 1024; i += 256) {
        int t = i >> 5, v = i & 31;
        hvq_s[t][v] = g_hvq[(size_t)(t0 + t) * VD + v];
    }

    for (int c = 0; c < 8; c++) {
        __syncthreads();
        for (int i = tid; i < 4096; i += 256) {
            int d = i >> 5, v = i & 31;
            wpi_s[d][v] = Wpi[(size_t)(c * 128 + d) * VD + v];
        }
        __syncthreads();
#pragma unroll
        for (int sub = 0; sub < 4; sub++) {
            int dd = sub * 32 + lane;
            float bb = bpi[c * 128 + dd];
            float a0 = bb, a1 = bb, a2 = bb, a3 = bb;
#pragma unroll
            for (int vq = 0; vq < 32; vq += 4) {
                float4 w4 = *(const float4*)&wpi_s[dd][vq];
                float4 h0 = *(const float4*)&hvq_s[tl + 0][vq];
                float4 h1 = *(const float4*)&hvq_s[tl + 1][vq];
                float4 h2 = *(const float4*)&hvq_s[tl + 2][vq];
                float4 h3 = *(const float4*)&hvq_s[tl + 3][vq];
                a0 += w4.x * h0.x + w4.y * h0.y + w4.z * h0.z + w4.w * h0.w;
                a1 += w4.x * h1.x + w4.y * h1.y + w4.z * h1.z + w4.w * h1.w;
                a2 += w4.x * h2.x + w4.y * h2.y + w4.z * h2.z + w4.w * h2.w;
                a3 += w4.x * h3.x + w4.y * h3.y + w4.z * h3.z + w4.w * h3.w;
            }
            out[(size_t)(t0 + tl + 0) * DIM + c * 128 + dd] = a0;
            out[(size_t)(t0 + tl + 1) * DIM + c * 128 + dd] = a1;
            out[(size_t)(t0 + tl + 2) * DIM + c * 128 + dd] = a2;
            out[(size_t)(t0 + tl + 3) * DIM + c * 128 + dd] = a3;
        }
    }
}

// ---------------- Kernel E: tail (codes as float + vq_loss=0) ----------------
__global__ void k_tail(float* __restrict__ out, int write_loss) {
    int i = blockIdx.x * blockDim.x + threadIdx.x;
    if (i < NTOK) out[(size_t)NTOK * DIM + i] = (float)g_code[i];
    if (i == 0 && write_loss) out[(size_t)NTOK * DIM + NTOK] = 0.0f;
}

// ---------------- launch ----------------
extern "C" void kernel_launch(void* const* d_in, const int* in_sizes, int n_in,
                              void* d_out, int out_size) {
    const float* h    = (const float*)d_in[0];
    const float* mask = (const float*)d_in[1];
    const float* Wp   = (const float*)d_in[2];
    const float* bp   = (const float*)d_in[3];
    const float* Wpi  = (const float*)d_in[4];
    const float* bpi  = (const float*)d_in[5];
    const float* emb  = (const float*)d_in[6];
    float* out = (float*)d_out;

    k_embnorm<<<512, 256>>>(emb);
    k_proj<<<256, 256>>>(h, Wp, bp);
    k_vq<<<512, 128>>>(mask);
    k_out<<<256, 256>>>(Wpi, bpi, out);

    long long need = (long long)NTOK * DIM;
    if ((long long)out_size >= need + NTOK) {
        int wl = ((long long)out_size >= need + NTOK + 1) ? 1 : 0;
        k_tail<<<(NTOK + 255) / 256, 256>>>(out, wl);
    }
}

// round 3
// speedup vs baseline: 2.1988x; 2.1988x over previous
#include <cuda_runtime.h>
#include <cuda_fp16.h>
#include <math.h>
#include <stdint.h>

#define NTOK 8192
#define DIM  1024
#define VD   32
#define KCB  4096

// ---------------- device scratch ----------------
__device__ __half g_ehl[KCB * 64];    // codebook normalized: [k][0:32)=hi, [32:64)=lo
__device__ __half g_hphl[NTOK * 64];  // hp normalized:       [t][0:32)=hi, [32:64)=lo
__device__ float  g_hvq[NTOK * VD];
__device__ int    g_code[NTOK];

// ---------------- helpers ----------------
__device__ __forceinline__ float warpSum(float v) {
#pragma unroll
    for (int o = 16; o; o >>= 1) v += __shfl_xor_sync(0xffffffffu, v, o);
    return v;
}
__device__ __forceinline__ uint32_t smaddr(const void* p) {
    return (uint32_t)__cvta_generic_to_shared(p);
}
__device__ __forceinline__ void ldmx4(uint32_t* r, uint32_t a) {
    asm volatile("ldmatrix.sync.aligned.m8n8.x4.shared.b16 {%0,%1,%2,%3}, [%4];"
                 : "=r"(r[0]), "=r"(r[1]), "=r"(r[2]), "=r"(r[3]) : "r"(a));
}
__device__ __forceinline__ void ldmx4t(uint32_t* r, uint32_t a) {
    asm volatile("ldmatrix.sync.aligned.m8n8.x4.trans.shared.b16 {%0,%1,%2,%3}, [%4];"
                 : "=r"(r[0]), "=r"(r[1]), "=r"(r[2]), "=r"(r[3]) : "r"(a));
}
__device__ __forceinline__ void mmaf16(float* c, const uint32_t* a, const uint32_t* b) {
    asm volatile("mma.sync.aligned.m16n8k16.row.col.f32.f16.f16.f32 "
                 "{%0,%1,%2,%3}, {%4,%5,%6,%7}, {%8,%9}, {%0,%1,%2,%3};"
                 : "+f"(c[0]), "+f"(c[1]), "+f"(c[2]), "+f"(c[3])
                 : "r"(a[0]), "r"(a[1]), "r"(a[2]), "r"(a[3]), "r"(b[0]), "r"(b[1]));
}
__device__ __forceinline__ float ex2f(float x) {
    float y; asm("ex2.approx.ftz.f32 %0, %1;" : "=f"(y) : "f"(x)); return y;
}
__device__ __forceinline__ uint32_t packh2(float lo, float hi) {
    uint32_t r; asm("cvt.rn.f16x2.f32 %0, %1, %2;" : "=r"(r) : "f"(hi), "f"(lo)); return r;
}

// ---------------- Kernel A: normalize codebook rows -> fp16 hi/lo ----------------
__global__ void k_embnorm(const float* __restrict__ emb) {
    int row  = blockIdx.x * 8 + (threadIdx.x >> 5);
    int lane = threadIdx.x & 31;
    float x  = emb[row * VD + lane];
    float ss = warpSum(x * x);
    float xn = x * rsqrtf(ss);
    __half hi = __float2half_rn(xn);
    float  lo = xn - __half2float(hi);
    g_ehl[(size_t)row * 64 + lane]      = hi;
    g_ehl[(size_t)row * 64 + 32 + lane] = __float2half_rn(lo);
}

// ---------------- Kernel B: hp = normalize(h @ Wp^T + bp) -> fp16 hi/lo ----------------
__global__ void k_proj(const float* __restrict__ h,
                       const float* __restrict__ Wp,
                       const float* __restrict__ bp) {
    __shared__ __align__(16) float wp_s[32][128];
    __shared__ __align__(16) float h_s[32][132];
    __shared__ __align__(16) float hpbuf[32][33];

    int tid = threadIdx.x, warp = tid >> 5, lane = tid & 31;
    int t0 = blockIdx.x * 32;
    int v0 = warp * 4;
    float acc0 = 0.f, acc1 = 0.f, acc2 = 0.f, acc3 = 0.f;

    for (int c = 0; c < 8; c++) {
        __syncthreads();
#pragma unroll
        for (int i = tid; i < 4096; i += 256) {
            int v = i >> 7, d = i & 127;
            wp_s[v][d] = Wp[v * DIM + c * 128 + d];
        }
#pragma unroll
        for (int i = tid; i < 4096; i += 256) {
            int t = i >> 7, d = i & 127;
            h_s[t][d] = h[(size_t)(t0 + t) * DIM + c * 128 + d];
        }
        __syncthreads();
#pragma unroll 4
        for (int dq = 0; dq < 128; dq += 4) {
            float4 hv = *(const float4*)&h_s[lane][dq];
            float4 w0 = *(const float4*)&wp_s[v0 + 0][dq];
            float4 w1 = *(const float4*)&wp_s[v0 + 1][dq];
            float4 w2 = *(const float4*)&wp_s[v0 + 2][dq];
            float4 w3 = *(const float4*)&wp_s[v0 + 3][dq];
            acc0 += hv.x * w0.x + hv.y * w0.y + hv.z * w0.z + hv.w * w0.w;
            acc1 += hv.x * w1.x + hv.y * w1.y + hv.z * w1.z + hv.w * w1.w;
            acc2 += hv.x * w2.x + hv.y * w2.y + hv.z * w2.z + hv.w * w2.w;
            acc3 += hv.x * w3.x + hv.y * w3.y + hv.z * w3.z + hv.w * w3.w;
        }
    }
    __syncthreads();
    hpbuf[lane][v0 + 0] = acc0 + bp[v0 + 0];
    hpbuf[lane][v0 + 1] = acc1 + bp[v0 + 1];
    hpbuf[lane][v0 + 2] = acc2 + bp[v0 + 2];
    hpbuf[lane][v0 + 3] = acc3 + bp[v0 + 3];
    __syncthreads();
#pragma unroll
    for (int q = 0; q < 4; q++) {
        int t = warp * 4 + q;
        float x = hpbuf[t][lane];
        float ss = warpSum(x * x);
        float xn = x * rsqrtf(ss);
        __half hi = __float2half_rn(xn);
        float  lo = xn - __half2float(hi);
        g_hphl[(size_t)(t0 + t) * 64 + lane]      = hi;
        g_hphl[(size_t)(t0 + t) * 64 + 32 + lane] = __float2half_rn(lo);
    }
}

// ---------------- Kernel C: VQ core on tensor cores (mma.sync f16) ----------------
// grid 128, block 256 (8 warps). CTA: 64 tokens x all 4096 codes (32 chunks of 128).
// warp = (m-band mb = wid>>1 of 16 tokens) x (code-half nh = wid&1 of 64 codes/chunk).
__global__ void __launch_bounds__(256) k_vq(const float* __restrict__ attn_mask) {
    __shared__ __align__(16) __half e_s[128][72];   // [code][hi 0:32 | lo 32:64 | pad]
    __shared__ __align__(16) __half hp_s[64][72];
    __shared__ __align__(16) float  ys[64][33];
    __shared__ float zs[64];
    __shared__ float bvs[64];
    __shared__ int   bks[64];

    const int tid = threadIdx.x, wid = tid >> 5, lane = tid & 31;
    const int t0 = blockIdx.x * 64;
    const int mb = wid >> 1, nh = wid & 1;
    const int g  = lane >> 2, t4 = lane & 3;

    // load hp tile rows (64 x 128B)
    for (int i = tid; i < 512; i += 256) {
        int r = i >> 3, cc = i & 7;
        *(float4*)&hp_s[r][cc * 8] = ((const float4*)g_hphl)[(size_t)(t0 + r) * 8 + cc];
    }
    __syncthreads();

    // hoist A fragments (hp hi/lo, 2 ksteps each)
    uint32_t a_hi[2][4], a_lo[2][4];
    {
        int r = mb * 16 + ((lane >> 3) & 1) * 8 + (lane & 7);
        int cb = (lane >> 4) * 8;
        ldmx4(a_hi[0], smaddr(&hp_s[r][0  + cb]));
        ldmx4(a_hi[1], smaddr(&hp_s[r][16 + cb]));
        ldmx4(a_lo[0], smaddr(&hp_s[r][32 + cb]));
        ldmx4(a_lo[1], smaddr(&hp_s[r][48 + cb]));
    }

    float yacc[4][4];
#pragma unroll
    for (int i = 0; i < 4; i++)
#pragma unroll
        for (int q = 0; q < 4; q++) yacc[i][q] = 0.f;
    float z0 = 0.f, z1 = 0.f;
    float bv0 = -INFINITY, bv1 = -INFINITY;
    int   bk0 = 0, bk1 = 0;

    // precomputed ldmatrix source addresses (chunk-invariant)
    const int sb_row = nh * 64 + (lane & 7);                      // score B rows (per tile +j*8)
    const int sb_col = ((lane >> 3) & 1) * 8 + (lane >> 4) * 16;  // score B col
    const int ab_rofs = nh * 64 + ((lane >> 3) & 1) * 8 + (lane & 7);  // accum B rows (+kc*16)
    const int ab_c8   = (lane >> 4) * 8;                               // accum B col (+vtp*16)

    for (int c = 0; c < 32; c++) {
        __syncthreads();
        for (int i = tid; i < 1024; i += 256) {
            int r = i >> 3, cc = i & 7;
            *(float4*)&e_s[r][cc * 8] = ((const float4*)g_ehl)[(size_t)(c * 128 + r) * 8 + cc];
        }
        __syncthreads();

        // ---- score pass: 8 n8-tiles of codes ----
        uint32_t pk[8][2];
#pragma unroll
        for (int j = 0; j < 8; j++) {
            float s[4] = {0.f, 0.f, 0.f, 0.f};
            uint32_t bh[4], bl[4];
            uint32_t ad = smaddr(&e_s[sb_row + j * 8][sb_col]);
            ldmx4(bh, ad);
            ldmx4(bl, ad + 64);
            mmaf16(s, a_hi[0], bh + 0); mmaf16(s, a_hi[1], bh + 2);
            mmaf16(s, a_lo[0], bh + 0); mmaf16(s, a_lo[1], bh + 2);
            mmaf16(s, a_hi[0], bl + 0); mmaf16(s, a_hi[1], bl + 2);

            int code0 = c * 128 + nh * 64 + j * 8 + t4 * 2;
            if (s[0] > bv0) { bv0 = s[0]; bk0 = code0; }
            if (s[1] > bv0) { bv0 = s[1]; bk0 = code0 + 1; }
            if (s[2] > bv1) { bv1 = s[2]; bk1 = code0; }
            if (s[3] > bv1) { bv1 = s[3]; bk1 = code0 + 1; }
            // p = exp(2s-2) = 2^((s-1)*2/ln2)
            float p0 = ex2f(fmaf(s[0], 2.885390082f, -2.885390082f));
            float p1 = ex2f(fmaf(s[1], 2.885390082f, -2.885390082f));
            float p2 = ex2f(fmaf(s[2], 2.885390082f, -2.885390082f));
            float p3 = ex2f(fmaf(s[3], 2.885390082f, -2.885390082f));
            z0 += p0 + p1; z1 += p2 + p3;
            pk[j][0] = packh2(p0, p1);
            pk[j][1] = packh2(p2, p3);
        }

        // ---- accumulate pass: y += P @ (E_hi + E_lo) ----
#pragma unroll
        for (int kc = 0; kc < 4; kc++) {
            uint32_t A[4] = {pk[2*kc][0], pk[2*kc][1], pk[2*kc+1][0], pk[2*kc+1][1]};
            int crow = ab_rofs + kc * 16;
#pragma unroll
            for (int vtp = 0; vtp < 2; vtp++) {
                uint32_t bh[4], bl[4];
                uint32_t ad = smaddr(&e_s[crow][vtp * 16 + ab_c8]);
                ldmx4t(bh, ad);
                ldmx4t(bl, ad + 64);
                mmaf16(yacc[vtp*2+0], A, bh + 0); mmaf16(yacc[vtp*2+1], A, bh + 2);
                mmaf16(yacc[vtp*2+0], A, bl + 0); mmaf16(yacc[vtp*2+1], A, bl + 2);
            }
        }
    }

    // ---- quad reductions (rows g, g+8 within band) ----
    z0 += __shfl_xor_sync(0xffffffffu, z0, 1); z0 += __shfl_xor_sync(0xffffffffu, z0, 2);
    z1 += __shfl_xor_sync(0xffffffffu, z1, 1); z1 += __shfl_xor_sync(0xffffffffu, z1, 2);
#pragma unroll
    for (int o = 1; o <= 2; o <<= 1) {
        float ob = __shfl_xor_sync(0xffffffffu, bv0, o);
        int   ok = __shfl_xor_sync(0xffffffffu, bk0, o);
        if (ob > bv0 || (ob == bv0 && ok < bk0)) { bv0 = ob; bk0 = ok; }
        ob = __shfl_xor_sync(0xffffffffu, bv1, o);
        ok = __shfl_xor_sync(0xffffffffu, bk1, o);
        if (ob > bv1 || (ob == bv1 && ok < bk1)) { bv1 = ob; bk1 = ok; }
    }

    int r0 = mb * 16 + g, r1 = r0 + 8;
    if (nh == 1) {
        if (t4 == 0) {
            zs[r0] = z0; bvs[r0] = bv0; bks[r0] = bk0;
            zs[r1] = z1; bvs[r1] = bv1; bks[r1] = bk1;
        }
#pragma unroll
        for (int vt = 0; vt < 4; vt++) {
            int cc = vt * 8 + t4 * 2;
            ys[r0][cc] = yacc[vt][0]; ys[r0][cc + 1] = yacc[vt][1];
            ys[r1][cc] = yacc[vt][2]; ys[r1][cc + 1] = yacc[vt][3];
        }
    }
    __syncthreads();
    if (nh == 0) {
        float Z0 = z0 + zs[r0], Z1 = z1 + zs[r1];
        {   // merge argmax with other half
            float ob = bvs[r0]; int ok = bks[r0];
            if (ob > bv0 || (ob == bv0 && ok < bk0)) { bv0 = ob; bk0 = ok; }
            ob = bvs[r1]; ok = bks[r1];
            if (ob > bv1 || (ob == bv1 && ok < bk1)) { bv1 = ob; bk1 = ok; }
        }
        int tok0 = t0 + r0, tok1 = t0 + r1;
        float mk0 = attn_mask[tok0], mk1 = attn_mask[tok1];
        float inv0 = (mk0 == 1.0f) ? 1.0f / Z0 : 0.0f;
        float inv1 = (mk1 == 1.0f) ? 1.0f / Z1 : 0.0f;
#pragma unroll
        for (int vt = 0; vt < 4; vt++) {
            int cc = vt * 8 + t4 * 2;
            g_hvq[(size_t)tok0 * VD + cc]     = (yacc[vt][0] + ys[r0][cc])     * inv0;
            g_hvq[(size_t)tok0 * VD + cc + 1] = (yacc[vt][1] + ys[r0][cc + 1]) * inv0;
            g_hvq[(size_t)tok1 * VD + cc]     = (yacc[vt][2] + ys[r1][cc])     * inv1;
            g_hvq[(size_t)tok1 * VD + cc + 1] = (yacc[vt][3] + ys[r1][cc + 1]) * inv1;
        }
        if (t4 == 0) {
            g_code[tok0] = (mk0 == 1.0f) ? bk0 : 0;
            g_code[tok1] = (mk1 == 1.0f) ? bk1 : 0;
        }
    }
}

// ---------------- Kernel D: quantized = g_hvq @ Wpi^T + bpi ----------------
__global__ void k_out(const float* __restrict__ Wpi,
                      const float* __restrict__ bpi,
                      float* __restrict__ out) {
    __shared__ __align__(16) float wpi_s[128][36];
    __shared__ __align__(16) float hvq_s[32][32];

    int tid = threadIdx.x, warp = tid >> 5, lane = tid & 31;
    int t0 = blockIdx.x * 32;
    int tl = warp * 4;

    for (int i = tid; i < 1024; i += 256) {
        int t = i >> 5, v = i & 31;
        hvq_s[t][v] = g_hvq[(size_t)(t0 + t) * VD + v];
    }

    for (int c = 0; c < 8; c++) {
        __syncthreads();
        for (int i = tid; i < 4096; i += 256) {
            int d = i >> 5, v = i & 31;
            wpi_s[d][v] = Wpi[(size_t)(c * 128 + d) * VD + v];
        }
        __syncthreads();
#pragma unroll
        for (int sub = 0; sub < 4; sub++) {
            int dd = sub * 32 + lane;
            float bb = bpi[c * 128 + dd];
            float a0 = bb, a1 = bb, a2 = bb, a3 = bb;
#pragma unroll
            for (int vq = 0; vq < 32; vq += 4) {
                float4 w4 = *(const float4*)&wpi_s[dd][vq];
                float4 h0 = *(const float4*)&hvq_s[tl + 0][vq];
                float4 h1 = *(const float4*)&hvq_s[tl + 1][vq];
                float4 h2 = *(const float4*)&hvq_s[tl + 2][vq];
                float4 h3 = *(const float4*)&hvq_s[tl + 3][vq];
                a0 += w4.x * h0.x + w4.y * h0.y + w4.z * h0.z + w4.w * h0.w;
                a1 += w4.x * h1.x + w4.y * h1.y + w4.z * h1.z + w4.w * h1.w;
                a2 += w4.x * h2.x + w4.y * h2.y + w4.z * h2.z + w4.w * h2.w;
                a3 += w4.x * h3.x + w4.y * h3.y + w4.z * h3.z + w4.w * h3.w;
            }
            out[(size_t)(t0 + tl + 0) * DIM + c * 128 + dd] = a0;
            out[(size_t)(t0 + tl + 1) * DIM + c * 128 + dd] = a1;
            out[(size_t)(t0 + tl + 2) * DIM + c * 128 + dd] = a2;
            out[(size_t)(t0 + tl + 3) * DIM + c * 128 + dd] = a3;
        }
    }
}

// ---------------- Kernel E: tail ----------------
__global__ void k_tail(float* __restrict__ out, int write_loss) {
    int i = blockIdx.x * blockDim.x + threadIdx.x;
    if (i < NTOK) out[(size_t)NTOK * DIM + i] = (float)g_code[i];
    if (i == 0 && write_loss) out[(size_t)NTOK * DIM + NTOK] = 0.0f;
}

// ---------------- launch ----------------
extern "C" void kernel_launch(void* const* d_in, const int* in_sizes, int n_in,
                              void* d_out, int out_size) {
    const float* h    = (const float*)d_in[0];
    const float* mask = (const float*)d_in[1];
    const float* Wp   = (const float*)d_in[2];
    const float* bp   = (const float*)d_in[3];
    const float* Wpi  = (const float*)d_in[4];
    const float* bpi  = (const float*)d_in[5];
    const float* emb  = (const float*)d_in[6];
    float* out = (float*)d_out;

    k_embnorm<<<512, 256>>>(emb);
    k_proj<<<256, 256>>>(h, Wp, bp);
    k_vq<<<128, 256>>>(mask);
    k_out<<<256, 256>>>(Wpi, bpi, out);

    long long need = (long long)NTOK * DIM;
    if ((long long)out_size >= need + NTOK) {
        int wl = ((long long)out_size >= need + NTOK + 1) ? 1 : 0;
        k_tail<<<(NTOK + 255) / 256, 256>>>(out, wl);
    }
}

// round 5
// speedup vs baseline: 2.9675x; 1.3496x over previous
#include <cuda_runtime.h>
#include <cuda_fp16.h>
#include <math.h>
#include <stdint.h>

#define NTOK 8192
#define DIM  1024
#define VD   32
#define KCB  4096

// ---------------- device scratch ----------------
__device__ __half g_ehl[KCB * 64];    // codebook normalized: [k][0:32)=hi, [32:64)=lo
__device__ __half g_hphl[NTOK * 64];  // hp normalized:       [t][0:32)=hi, [32:64)=lo
__device__ float  g_py[2 * NTOK * VD];  // partial unnormalized y per ksplit
__device__ float  g_pz[2 * NTOK];       // partial Z
__device__ float  g_pbv[2 * NTOK];      // partial argmax value
__device__ int    g_pbk[2 * NTOK];      // partial argmax index

// ---------------- helpers ----------------
__device__ __forceinline__ float warpSum(float v) {
#pragma unroll
    for (int o = 16; o; o >>= 1) v += __shfl_xor_sync(0xffffffffu, v, o);
    return v;
}
__device__ __forceinline__ uint32_t smaddr(const void* p) {
    return (uint32_t)__cvta_generic_to_shared(p);
}
__device__ __forceinline__ void ldmx4(uint32_t* r, uint32_t a) {
    asm volatile("ldmatrix.sync.aligned.m8n8.x4.shared.b16 {%0,%1,%2,%3}, [%4];"
                 : "=r"(r[0]), "=r"(r[1]), "=r"(r[2]), "=r"(r[3]) : "r"(a));
}
__device__ __forceinline__ void ldmx4t(uint32_t* r, uint32_t a) {
    asm volatile("ldmatrix.sync.aligned.m8n8.x4.trans.shared.b16 {%0,%1,%2,%3}, [%4];"
                 : "=r"(r[0]), "=r"(r[1]), "=r"(r[2]), "=r"(r[3]) : "r"(a));
}
__device__ __forceinline__ void mmaf16(float* c, const uint32_t* a, const uint32_t* b) {
    asm volatile("mma.sync.aligned.m16n8k16.row.col.f32.f16.f16.f32 "
                 "{%0,%1,%2,%3}, {%4,%5,%6,%7}, {%8,%9}, {%0,%1,%2,%3};"
                 : "+f"(c[0]), "+f"(c[1]), "+f"(c[2]), "+f"(c[3])
                 : "r"(a[0]), "r"(a[1]), "r"(a[2]), "r"(a[3]), "r"(b[0]), "r"(b[1]));
}
__device__ __forceinline__ float ex2f(float x) {
    float y; asm("ex2.approx.ftz.f32 %0, %1;" : "=f"(y) : "f"(x)); return y;
}
__device__ __forceinline__ uint32_t packh2(float lo, float hi) {
    uint32_t r; asm("cvt.rn.f16x2.f32 %0, %1, %2;" : "=r"(r) : "f"(hi), "f"(lo)); return r;
}
__device__ __forceinline__ void cpa16(uint32_t dst, const void* src) {
    asm volatile("cp.async.cg.shared.global [%0], [%1], 16;" :: "r"(dst), "l"(src));
}
#define CP_COMMIT() asm volatile("cp.async.commit_group;" ::: "memory")
#define CP_WAIT(n)  asm volatile("cp.async.wait_group %0;" :: "n"(n) : "memory")

// ---------------- Kernel A: normalize codebook rows -> fp16 hi/lo ----------------
__global__ void k_embnorm(const float* __restrict__ emb) {
    int row  = blockIdx.x * 8 + (threadIdx.x >> 5);
    int lane = threadIdx.x & 31;
    float x  = emb[row * VD + lane];
    float ss = warpSum(x * x);
    float xn = x * rsqrtf(ss);
    __half hi = __float2half_rn(xn);
    float  lo = xn - __half2float(hi);
    g_ehl[(size_t)row * 64 + lane]      = hi;
    g_ehl[(size_t)row * 64 + 32 + lane] = __float2half_rn(lo);
}

// ---------------- Kernel B: hp = normalize(h @ Wp^T + bp) -> fp16 hi/lo ----------------
__global__ void k_proj(const float* __restrict__ h,
                       const float* __restrict__ Wp,
                       const float* __restrict__ bp) {
    __shared__ __align__(16) float wp_s[32][128];
    __shared__ __align__(16) float h_s[32][132];
    __shared__ __align__(16) float hpbuf[32][33];

    int tid = threadIdx.x, warp = tid >> 5, lane = tid & 31;
    int t0 = blockIdx.x * 32;
    int v0 = warp * 4;
    float acc0 = 0.f, acc1 = 0.f, acc2 = 0.f, acc3 = 0.f;

    for (int c = 0; c < 8; c++) {
        __syncthreads();
#pragma unroll
        for (int i = tid; i < 4096; i += 256) {
            int v = i >> 7, d = i & 127;
            wp_s[v][d] = Wp[v * DIM + c * 128 + d];
        }
#pragma unroll
        for (int i = tid; i < 4096; i += 256) {
            int t = i >> 7, d = i & 127;
            h_s[t][d] = h[(size_t)(t0 + t) * DIM + c * 128 + d];
        }
        __syncthreads();
#pragma unroll 4
        for (int dq = 0; dq < 128; dq += 4) {
            float4 hv = *(const float4*)&h_s[lane][dq];
            float4 w0 = *(const float4*)&wp_s[v0 + 0][dq];
            float4 w1 = *(const float4*)&wp_s[v0 + 1][dq];
            float4 w2 = *(const float4*)&wp_s[v0 + 2][dq];
            float4 w3 = *(const float4*)&wp_s[v0 + 3][dq];
            acc0 += hv.x * w0.x + hv.y * w0.y + hv.z * w0.z + hv.w * w0.w;
            acc1 += hv.x * w1.x + hv.y * w1.y + hv.z * w1.z + hv.w * w1.w;
            acc2 += hv.x * w2.x + hv.y * w2.y + hv.z * w2.z + hv.w * w2.w;
            acc3 += hv.x * w3.x + hv.y * w3.y + hv.z * w3.z + hv.w * w3.w;
        }
    }
    __syncthreads();
    hpbuf[lane][v0 + 0] = acc0 + bp[v0 + 0];
    hpbuf[lane][v0 + 1] = acc1 + bp[v0 + 1];
    hpbuf[lane][v0 + 2] = acc2 + bp[v0 + 2];
    hpbuf[lane][v0 + 3] = acc3 + bp[v0 + 3];
    __syncthreads();
#pragma unroll
    for (int q = 0; q < 4; q++) {
        int t = warp * 4 + q;
        float x = hpbuf[t][lane];
        float ss = warpSum(x * x);
        float xn = x * rsqrtf(ss);
        __half hi = __float2half_rn(xn);
        float  lo = xn - __half2float(hi);
        g_hphl[(size_t)(t0 + t) * 64 + lane]      = hi;
        g_hphl[(size_t)(t0 + t) * 64 + 32 + lane] = __float2half_rn(lo);
    }
}

// ---------------- Kernel C: VQ core on tensor cores (mma.sync f16) ----------------
// grid 256 = 128 token-tiles x 2 code-splits; block 256 (8 warps).
// CTA: 64 tokens x 2048 codes (16 chunks of 128). Double-buffered e via cp.async.
__global__ void __launch_bounds__(256, 2) k_vq(void) {
    struct Epi { float ys[64][33]; float zs[64]; float bvs[64]; int bks[64]; };
    __shared__ __align__(16) unsigned char pool_[2 * 128 * 72 * 2];  // 36864B
    __half (*e_s)[128][72] = reinterpret_cast<__half(*)[128][72]>(pool_);
    Epi* epi = reinterpret_cast<Epi*>(pool_);
    __shared__ __align__(16) __half hp_s[64][72];

    const int tid = threadIdx.x, wid = tid >> 5, lane = tid & 31;
    const int tileIdx = blockIdx.x >> 1;
    const int ks = blockIdx.x & 1;
    const int t0 = tileIdx * 64;
    const int cbase = ks * 16;           // chunk base (16 chunks of 128 codes)
    const int mb = wid >> 1, nh = wid & 1;
    const int g  = lane >> 2, t4 = lane & 3;

    // prefetch chunk 0 into buf 0
    {
        int i0 = tid, r = i0 >> 3, c8 = i0 & 7;
        cpa16(smaddr(&e_s[0][r][c8 * 8]),
              (const char*)g_ehl + ((size_t)(cbase * 128 + r) * 64 + c8 * 8) * 2);
        int i1 = tid + 256; r = i1 >> 3; c8 = i1 & 7;
        cpa16(smaddr(&e_s[0][r][c8 * 8]),
              (const char*)g_ehl + ((size_t)(cbase * 128 + r) * 64 + c8 * 8) * 2);
        int i2 = tid + 512; r = i2 >> 3; c8 = i2 & 7;
        cpa16(smaddr(&e_s[0][r][c8 * 8]),
              (const char*)g_ehl + ((size_t)(cbase * 128 + r) * 64 + c8 * 8) * 2);
        int i3 = tid + 768; r = i3 >> 3; c8 = i3 & 7;
        cpa16(smaddr(&e_s[0][r][c8 * 8]),
              (const char*)g_ehl + ((size_t)(cbase * 128 + r) * 64 + c8 * 8) * 2);
        CP_COMMIT();
    }

    // load hp tile rows (64 x 128B)
    for (int i = tid; i < 512; i += 256) {
        int r = i >> 3, cc = i & 7;
        *(float4*)&hp_s[r][cc * 8] = ((const float4*)g_hphl)[(size_t)(t0 + r) * 8 + cc];
    }
    __syncthreads();

    // hoist A fragments (hp hi/lo, 2 ksteps each)
    uint32_t a_hi[2][4], a_lo[2][4];
    {
        int r = mb * 16 + ((lane >> 3) & 1) * 8 + (lane & 7);
        int cb = (lane >> 4) * 8;
        ldmx4(a_hi[0], smaddr(&hp_s[r][0  + cb]));
        ldmx4(a_hi[1], smaddr(&hp_s[r][16 + cb]));
        ldmx4(a_lo[0], smaddr(&hp_s[r][32 + cb]));
        ldmx4(a_lo[1], smaddr(&hp_s[r][48 + cb]));
    }

    float yacc[4][4];
#pragma unroll
    for (int i = 0; i < 4; i++)
#pragma unroll
        for (int q = 0; q < 4; q++) yacc[i][q] = 0.f;
    float z0 = 0.f, z1 = 0.f;
    float bv0 = -INFINITY, bv1 = -INFINITY;
    int   bk0 = 0, bk1 = 0;

    const int sb_row = nh * 64 + (lane & 7);
    const int sb_col = ((lane >> 3) & 1) * 8 + (lane >> 4) * 16;
    const int ab_rofs = nh * 64 + ((lane >> 3) & 1) * 8 + (lane & 7);
    const int ab_c8   = (lane >> 4) * 8;

    for (int ci = 0; ci < 16; ci++) {
        const int cur = ci & 1;
        const int c = cbase + ci;
        // prefetch next chunk into other buffer (freed by previous end-of-iter sync)
        if (ci + 1 < 16) {
            int nb = 1 - cur;
            const char* src = (const char*)g_ehl + (size_t)(c + 1) * 128 * 128;
#pragma unroll
            for (int j = 0; j < 4; j++) {
                int i = tid + j * 256, r = i >> 3, c8 = i & 7;
                cpa16(smaddr(&e_s[nb][r][c8 * 8]), src + ((size_t)r * 64 + c8 * 8) * 2);
            }
            CP_COMMIT();
            CP_WAIT(1);
        } else {
            CP_WAIT(0);
        }
        __syncthreads();

        // ---- score pass: 8 n8-tiles of codes ----
        uint32_t pk[8][2];
#pragma unroll
        for (int j = 0; j < 8; j++) {
            float s[4] = {0.f, 0.f, 0.f, 0.f};
            uint32_t bh[4], bl[4];
            uint32_t ad = smaddr(&e_s[cur][sb_row + j * 8][sb_col]);
            ldmx4(bh, ad);
            ldmx4(bl, ad + 64);
            mmaf16(s, a_hi[0], bh + 0); mmaf16(s, a_hi[1], bh + 2);
            mmaf16(s, a_lo[0], bh + 0); mmaf16(s, a_lo[1], bh + 2);
            mmaf16(s, a_hi[0], bl + 0); mmaf16(s, a_hi[1], bl + 2);

            int code0 = c * 128 + nh * 64 + j * 8 + t4 * 2;
            if (s[0] > bv0) { bv0 = s[0]; bk0 = code0; }
            if (s[1] > bv0) { bv0 = s[1]; bk0 = code0 + 1; }
            if (s[2] > bv1) { bv1 = s[2]; bk1 = code0; }
            if (s[3] > bv1) { bv1 = s[3]; bk1 = code0 + 1; }
            float p0 = ex2f(fmaf(s[0], 2.885390082f, -2.885390082f));
            float p1 = ex2f(fmaf(s[1], 2.885390082f, -2.885390082f));
            float p2 = ex2f(fmaf(s[2], 2.885390082f, -2.885390082f));
            float p3 = ex2f(fmaf(s[3], 2.885390082f, -2.885390082f));
            z0 += p0 + p1; z1 += p2 + p3;
            pk[j][0] = packh2(p0, p1);
            pk[j][1] = packh2(p2, p3);
        }

        // ---- accumulate pass: y += P @ (E_hi + E_lo) ----
#pragma unroll
        for (int kc = 0; kc < 4; kc++) {
            uint32_t A[4] = {pk[2*kc][0], pk[2*kc][1], pk[2*kc+1][0], pk[2*kc+1][1]};
            int crow = ab_rofs + kc * 16;
#pragma unroll
            for (int vtp = 0; vtp < 2; vtp++) {
                uint32_t bh[4], bl[4];
                uint32_t ad = smaddr(&e_s[cur][crow][vtp * 16 + ab_c8]);
                ldmx4t(bh, ad);
                ldmx4t(bl, ad + 64);
                mmaf16(yacc[vtp*2+0], A, bh + 0); mmaf16(yacc[vtp*2+1], A, bh + 2);
                mmaf16(yacc[vtp*2+0], A, bl + 0); mmaf16(yacc[vtp*2+1], A, bl + 2);
            }
        }
        __syncthreads();
    }

    // ---- quad reductions ----
    z0 += __shfl_xor_sync(0xffffffffu, z0, 1); z0 += __shfl_xor_sync(0xffffffffu, z0, 2);
    z1 += __shfl_xor_sync(0xffffffffu, z1, 1); z1 += __shfl_xor_sync(0xffffffffu, z1, 2);
#pragma unroll
    for (int o = 1; o <= 2; o <<= 1) {
        float ob = __shfl_xor_sync(0xffffffffu, bv0, o);
        int   ok = __shfl_xor_sync(0xffffffffu, bk0, o);
        if (ob > bv0 || (ob == bv0 && ok < bk0)) { bv0 = ob; bk0 = ok; }
        ob = __shfl_xor_sync(0xffffffffu, bv1, o);
        ok = __shfl_xor_sync(0xffffffffu, bk1, o);
        if (ob > bv1 || (ob == bv1 && ok < bk1)) { bv1 = ob; bk1 = ok; }
    }

    int r0 = mb * 16 + g, r1 = r0 + 8;
    if (nh == 1) {
        if (t4 == 0) {
            epi->zs[r0] = z0; epi->bvs[r0] = bv0; epi->bks[r0] = bk0;
            epi->zs[r1] = z1; epi->bvs[r1] = bv1; epi->bks[r1] = bk1;
        }
#pragma unroll
        for (int vt = 0; vt < 4; vt++) {
            int cc = vt * 8 + t4 * 2;
            epi->ys[r0][cc] = yacc[vt][0]; epi->ys[r0][cc + 1] = yacc[vt][1];
            epi->ys[r1][cc] = yacc[vt][2]; epi->ys[r1][cc + 1] = yacc[vt][3];
        }
    }
    __syncthreads();
    if (nh == 0) {
        float Z0 = z0 + epi->zs[r0], Z1 = z1 + epi->zs[r1];
        {
            float ob = epi->bvs[r0]; int ok = epi->bks[r0];
            if (ob > bv0 || (ob == bv0 && ok < bk0)) { bv0 = ob; bk0 = ok; }
            ob = epi->bvs[r1]; ok = epi->bks[r1];
            if (ob > bv1 || (ob == bv1 && ok < bk1)) { bv1 = ob; bk1 = ok; }
        }
        int tok0 = t0 + r0, tok1 = t0 + r1;
        size_t base = (size_t)ks * NTOK;
#pragma unroll
        for (int vt = 0; vt < 4; vt++) {
            int cc = vt * 8 + t4 * 2;
            g_py[(base + tok0) * VD + cc]     = yacc[vt][0] + epi->ys[r0][cc];
            g_py[(base + tok0) * VD + cc + 1] = yacc[vt][1] + epi->ys[r0][cc + 1];
            g_py[(base + tok1) * VD + cc]     = yacc[vt][2] + epi->ys[r1][cc];
            g_py[(base + tok1) * VD + cc + 1] = yacc[vt][3] + epi->ys[r1][cc + 1];
        }
        if (t4 == 0) {
            g_pz[base + tok0] = Z0;  g_pz[base + tok1] = Z1;
            g_pbv[base + tok0] = bv0; g_pbv[base + tok1] = bv1;
            g_pbk[base + tok0] = bk0; g_pbk[base + tok1] = bk1;
        }
    }
}

// ---------------- Kernel D: merge partials + quantized = hvq @ Wpi^T + bpi ----------------
__global__ void k_out(const float* __restrict__ Wpi,
                      const float* __restrict__ bpi,
                      const float* __restrict__ attn_mask,
                      float* __restrict__ out) {
    __shared__ __align__(16) float wpi_s[128][36];
    __shared__ __align__(16) float hvq_s[32][32];

    int tid = threadIdx.x, warp = tid >> 5, lane = tid & 31;
    int t0 = blockIdx.x * 32;
    int tl = warp * 4;

    for (int i = tid; i < 1024; i += 256) {
        int t = i >> 5, v = i & 31;
        int tok = t0 + t;
        float y = g_py[(size_t)tok * VD + v] + g_py[(size_t)(NTOK + tok) * VD + v];
        float Z = g_pz[tok] + g_pz[NTOK + tok];
        float mk = attn_mask[tok];
        hvq_s[t][v] = (mk == 1.0f) ? y / Z : 0.0f;
    }

    for (int c = 0; c < 8; c++) {
        __syncthreads();
        for (int i = tid; i < 4096; i += 256) {
            int d = i >> 5, v = i & 31;
            wpi_s[d][v] = Wpi[(size_t)(c * 128 + d) * VD + v];
        }
        __syncthreads();
#pragma unroll
        for (int sub = 0; sub < 4; sub++) {
            int dd = sub * 32 + lane;
            float bb = bpi[c * 128 + dd];
            float a0 = bb, a1 = bb, a2 = bb, a3 = bb;
#pragma unroll
            for (int vq = 0; vq < 32; vq += 4) {
                float4 w4 = *(const float4*)&wpi_s[dd][vq];
                float4 h0 = *(const float4*)&hvq_s[tl + 0][vq];
                float4 h1 = *(const float4*)&hvq_s[tl + 1][vq];
                float4 h2 = *(const float4*)&hvq_s[tl + 2][vq];
                float4 h3 = *(const float4*)&hvq_s[tl + 3][vq];
                a0 += w4.x * h0.x + w4.y * h0.y + w4.z * h0.z + w4.w * h0.w;
                a1 += w4.x * h1.x + w4.y * h1.y + w4.z * h1.z + w4.w * h1.w;
                a2 += w4.x * h2.x + w4.y * h2.y + w4.z * h2.z + w4.w * h2.w;
                a3 += w4.x * h3.x + w4.y * h3.y + w4.z * h3.z + w4.w * h3.w;
            }
            out[(size_t)(t0 + tl + 0) * DIM + c * 128 + dd] = a0;
            out[(size_t)(t0 + tl + 1) * DIM + c * 128 + dd] = a1;
            out[(size_t)(t0 + tl + 2) * DIM + c * 128 + dd] = a2;
            out[(size_t)(t0 + tl + 3) * DIM + c * 128 + dd] = a3;
        }
    }
}

// ---------------- Kernel E: tail (merge argmax, codes as float + loss) ----------------
__global__ void k_tail(const float* __restrict__ attn_mask,
                       float* __restrict__ out, int write_loss) {
    int i = blockIdx.x * blockDim.x + threadIdx.x;
    if (i < NTOK) {
        float bv0 = g_pbv[i], bv1 = g_pbv[NTOK + i];
        int   bk0 = g_pbk[i], bk1 = g_pbk[NTOK + i];
        int code = (bv1 > bv0) ? bk1 : bk0;   // tie -> lower index (split 0)
        float mk = attn_mask[i];
        out[(size_t)NTOK * DIM + i] = (mk == 1.0f) ? (float)code : 0.0f;
    }
    if (i == 0 && write_loss) out[(size_t)NTOK * DIM + NTOK] = 0.0f;
}

// ---------------- launch ----------------
extern "C" void kernel_launch(void* const* d_in, const int* in_sizes, int n_in,
                              void* d_out, int out_size) {
    const float* h    = (const float*)d_in[0];
    const float* mask = (const float*)d_in[1];
    const float* Wp   = (const float*)d_in[2];
    const float* bp   = (const float*)d_in[3];
    const float* Wpi  = (const float*)d_in[4];
    const float* bpi  = (const float*)d_in[5];
    const float* emb  = (const float*)d_in[6];
    float* out = (float*)d_out;

    k_embnorm<<<512, 256>>>(emb);
    k_proj<<<256, 256>>>(h, Wp, bp);
    k_vq<<<256, 256>>>();
    k_out<<<256, 256>>>(Wpi, bpi, mask, out);

    long long need = (long long)NTOK * DIM;
    if ((long long)out_size >= need + NTOK) {
        int wl = ((long long)out_size >= need + NTOK + 1) ? 1 : 0;
        k_tail<<<(NTOK + 255) / 256, 256>>>(mask, out, wl);
    }
}

// round 8
// speedup vs baseline: 4.8002x; 1.6176x over previous
#include <cuda_runtime.h>
#include <cuda_fp16.h>
#include <math.h>
#include <stdint.h>

#define NTOK 8192
#define DIM  1024
#define VD   32
#define KCB  4096

// ---------------- device scratch ----------------
__device__ __half g_ehl[KCB * 64];      // codebook normalized: [k][hi 0:32 | lo 32:64]
__device__ __half g_hphl[NTOK * 64];    // hp normalized:       [t][hi 0:32 | lo 32:64]
__device__ __half g_wphl[32 * 2048];    // Wp  split: [v][hi k 0:1024 | lo k 1024:2048]
__device__ __half g_wpihl[1024 * 64];   // Wpi split: [d][hi v 0:32 | lo v 32:64]
__device__ float  g_py[2 * NTOK * VD];  // partial unnormalized y per ksplit
__device__ float  g_pz[2 * NTOK];       // partial Z
__device__ float  g_pbv[2 * NTOK];      // partial argmax value
__device__ int    g_pbk[2 * NTOK];      // partial argmax index

// ---------------- helpers ----------------
__device__ __forceinline__ float warpSum(float v) {
#pragma unroll
    for (int o = 16; o; o >>= 1) v += __shfl_xor_sync(0xffffffffu, v, o);
    return v;
}
__device__ __forceinline__ uint32_t smaddr(const void* p) {
    return (uint32_t)__cvta_generic_to_shared(p);
}
__device__ __forceinline__ void ldmx4(uint32_t* r, uint32_t a) {
    asm volatile("ldmatrix.sync.aligned.m8n8.x4.shared.b16 {%0,%1,%2,%3}, [%4];"
                 : "=r"(r[0]), "=r"(r[1]), "=r"(r[2]), "=r"(r[3]) : "r"(a));
}
__device__ __forceinline__ void ldmx4t(uint32_t* r, uint32_t a) {
    asm volatile("ldmatrix.sync.aligned.m8n8.x4.trans.shared.b16 {%0,%1,%2,%3}, [%4];"
                 : "=r"(r[0]), "=r"(r[1]), "=r"(r[2]), "=r"(r[3]) : "r"(a));
}
__device__ __forceinline__ void mmaf16(float* c, const uint32_t* a, const uint32_t* b) {
    asm volatile("mma.sync.aligned.m16n8k16.row.col.f32.f16.f16.f32 "
                 "{%0,%1,%2,%3}, {%4,%5,%6,%7}, {%8,%9}, {%0,%1,%2,%3};"
                 : "+f"(c[0]), "+f"(c[1]), "+f"(c[2]), "+f"(c[3])
                 : "r"(a[0]), "r"(a[1]), "r"(a[2]), "r"(a[3]), "r"(b[0]), "r"(b[1]));
}
__device__ __forceinline__ float ex2f(float x) {
    float y; asm("ex2.approx.ftz.f32 %0, %1;" : "=f"(y) : "f"(x)); return y;
}
__device__ __forceinline__ uint32_t packh2(float lo, float hi) {
    uint32_t r; asm("cvt.rn.f16x2.f32 %0, %1, %2;" : "=r"(r) : "f"(hi), "f"(lo)); return r;
}
__device__ __forceinline__ void cpa16(uint32_t dst, const void* src) {
    asm volatile("cp.async.cg.shared.global [%0], [%1], 16;" :: "r"(dst), "l"(src));
}
#define CP_COMMIT() asm volatile("cp.async.commit_group;" ::: "memory")
#define CP_WAIT(n)  asm volatile("cp.async.wait_group %0;" :: "n"(n) : "memory")

// split a float into fp16 hi + lo
__device__ __forceinline__ void hsplit(float x, __half& hi, __half& lo) {
    hi = __float2half_rn(x);
    lo = __float2half_rn(x - __half2float(hi));
}

// ---------------- Kernel A: normalize codebook rows -> fp16 hi/lo ----------------
__global__ void k_embnorm(const float* __restrict__ emb) {
    int row  = blockIdx.x * 8 + (threadIdx.x >> 5);
    int lane = threadIdx.x & 31;
    float x  = emb[row * VD + lane];
    float ss = warpSum(x * x);
    float xn = x * rsqrtf(ss);
    __half hi, lo; hsplit(xn, hi, lo);
    g_ehl[(size_t)row * 64 + lane]      = hi;
    g_ehl[(size_t)row * 64 + 32 + lane] = lo;
}

// ---------------- Kernel A2: split Wp and Wpi to fp16 hi/lo ----------------
// grid 128 x block 256: 32768 threads, each 1 Wp elem + 1 Wpi elem.
__global__ void k_wprep(const float* __restrict__ Wp,
                        const float* __restrict__ Wpi) {
    int i = blockIdx.x * 256 + threadIdx.x;
    {   // Wp [32][1024]
        int v = i >> 10, k = i & 1023;
        __half hi, lo; hsplit(Wp[v * 1024 + k], hi, lo);
        g_wphl[(size_t)v * 2048 + k]        = hi;
        g_wphl[(size_t)v * 2048 + 1024 + k] = lo;
    }
    {   // Wpi [1024][32]
        int d = i >> 5, v = i & 31;
        __half hi, lo; hsplit(Wpi[d * 32 + v], hi, lo);
        g_wpihl[(size_t)d * 64 + v]      = hi;
        g_wpihl[(size_t)d * 64 + 32 + v] = lo;
    }
}

// ---------------- Kernel B: hp = normalize(h @ Wp^T + bp) on tensor cores ----------------
// grid 256, block 256 (8 warps). CTA: 32 tokens x 32 v, K=1024 in 16 chunks of 64.
// warp = (mb = wid>>2: 16-token band) x (nq = wid&3: 8 v).
__global__ void __launch_bounds__(256) k_proj(const float* __restrict__ h,
                                              const float* __restrict__ bp) {
    __shared__ __align__(16) __half ah[32][72];   // h hi   [tok][k 0:64]
    __shared__ __align__(16) __half al[32][72];   // h lo
    __shared__ __align__(16) __half wh[32][72];   // Wp hi  [v][k 0:64]
    __shared__ __align__(16) __half wl[32][72];   // Wp lo
    __shared__ __align__(16) float  hpb[32][36];

    const int tid = threadIdx.x, wid = tid >> 5, lane = tid & 31;
    const int t0 = blockIdx.x * 32;
    const int mb = wid >> 2, nq = wid & 3;
    const int g = lane >> 2, t4 = lane & 3;

    float c[4] = {0.f, 0.f, 0.f, 0.f};

    const int cvrow = tid >> 3;          // 0..31 token row
    const int cvseg = tid & 7;           // 8-col segment

    for (int ch = 0; ch < 16; ch++) {
        __syncthreads();
        // cp.async Wp chunk (hi+lo planes)
#pragma unroll
        for (int j = 0; j < 2; j++) {
            int i = tid + j * 256;
            int pl = i >> 8, r = (i >> 3) & 31, c8 = i & 7;
            cpa16(smaddr(pl ? &wl[r][c8 * 8] : &wh[r][c8 * 8]),
                  g_wphl + (size_t)r * 2048 + pl * 1024 + ch * 64 + c8 * 8);
        }
        CP_COMMIT();
        // load h fp32, split, store to smem
        {
            const float* src = h + (size_t)(t0 + cvrow) * DIM + ch * 64 + cvseg * 8;
#pragma unroll
            for (int q = 0; q < 2; q++) {
                float4 f = *(const float4*)(src + q * 4);
                __half h0, l0, h1, l1, h2, l2, h3, l3;
                hsplit(f.x, h0, l0); hsplit(f.y, h1, l1);
                hsplit(f.z, h2, l2); hsplit(f.w, h3, l3);
                __half hh[4] = {h0, h1, h2, h3};
                __half ll[4] = {l0, l1, l2, l3};
                *(uint2*)&ah[cvrow][cvseg * 8 + q * 4] = *(uint2*)hh;
                *(uint2*)&al[cvrow][cvseg * 8 + q * 4] = *(uint2*)ll;
            }
        }
        CP_WAIT(0);
        __syncthreads();

        // A fragments (4 ksteps hi, 4 lo)
        uint32_t a_hi[4][4], a_lo[4][4];
        {
            int r = mb * 16 + ((lane >> 3) & 1) * 8 + (lane & 7);
            int cb = (lane >> 4) * 8;
#pragma unroll
            for (int ks = 0; ks < 4; ks++) {
                ldmx4(a_hi[ks], smaddr(&ah[r][ks * 16 + cb]));
                ldmx4(a_lo[ks], smaddr(&al[r][ks * 16 + cb]));
            }
        }
        // B fragments: one n8 tile (v = nq*8..nq*8+7), k 0..63
        uint32_t bh_a[4], bh_b[4], bl_a[4], bl_b[4];
        {
            int r = nq * 8 + (lane & 7);
            int cc = ((lane >> 3) & 1) * 8 + (lane >> 4) * 16;
            uint32_t adh = smaddr(&wh[r][cc]);
            uint32_t adl = smaddr(&wl[r][cc]);
            ldmx4(bh_a, adh); ldmx4(bh_b, adh + 64);
            ldmx4(bl_a, adl); ldmx4(bl_b, adl + 64);
        }
        mmaf16(c, a_hi[0], bh_a + 0); mmaf16(c, a_hi[1], bh_a + 2);
        mmaf16(c, a_hi[2], bh_b + 0); mmaf16(c, a_hi[3], bh_b + 2);
        mmaf16(c, a_lo[0], bh_a + 0); mmaf16(c, a_lo[1], bh_a + 2);
        mmaf16(c, a_lo[2], bh_b + 0); mmaf16(c, a_lo[3], bh_b + 2);
        mmaf16(c, a_hi[0], bl_a + 0); mmaf16(c, a_hi[1], bl_a + 2);
        mmaf16(c, a_hi[2], bl_b + 0); mmaf16(c, a_hi[3], bl_b + 2);
    }

    // write C frags to smem
    {
        int r = mb * 16 + g, cc = nq * 8 + t4 * 2;
        hpb[r][cc] = c[0];     hpb[r][cc + 1] = c[1];
        hpb[r + 8][cc] = c[2]; hpb[r + 8][cc + 1] = c[3];
    }
    __syncthreads();
    // normalize: warp handles 4 tokens, lane = v
#pragma unroll
    for (int q = 0; q < 4; q++) {
        int t = wid * 4 + q;
        float x = hpb[t][lane] + bp[lane];
        float ss = warpSum(x * x);
        float xn = x * rsqrtf(ss);
        __half hi, lo; hsplit(xn, hi, lo);
        g_hphl[(size_t)(t0 + t) * 64 + lane]      = hi;
        g_hphl[(size_t)(t0 + t) * 64 + 32 + lane] = lo;
    }
}

// ---------------- Kernel C: VQ core on tensor cores (mma.sync f16) ----------------
// grid 256 = 128 token-tiles x 2 code-splits; block 256 (8 warps).
__global__ void __launch_bounds__(256, 2) k_vq(void) {
    struct Epi { float ys[64][33]; float zs[64]; float bvs[64]; int bks[64]; };
    __shared__ __align__(16) unsigned char pool_[2 * 128 * 72 * 2];  // 36864B
    __half (*e_s)[128][72] = reinterpret_cast<__half(*)[128][72]>(pool_);
    Epi* epi = reinterpret_cast<Epi*>(pool_);
    __shared__ __align__(16) __half hp_s[64][72];

    const int tid = threadIdx.x, wid = tid >> 5, lane = tid & 31;
    const int tileIdx = blockIdx.x >> 1;
    const int ks = blockIdx.x & 1;
    const int t0 = tileIdx * 64;
    const int cbase = ks * 16;
    const int mb = wid >> 1, nh = wid & 1;
    const int g  = lane >> 2, t4 = lane & 3;

    // prefetch chunk 0 into buf 0
#pragma unroll
    for (int j = 0; j < 4; j++) {
        int i = tid + j * 256, r = i >> 3, c8 = i & 7;
        cpa16(smaddr(&e_s[0][r][c8 * 8]),
              (const char*)g_ehl + ((size_t)(cbase * 128 + r) * 64 + c8 * 8) * 2);
    }
    CP_COMMIT();

    for (int i = tid; i < 512; i += 256) {
        int r = i >> 3, cc = i & 7;
        *(float4*)&hp_s[r][cc * 8] = ((const float4*)g_hphl)[(size_t)(t0 + r) * 8 + cc];
    }
    __syncthreads();

    uint32_t a_hi[2][4], a_lo[2][4];
    {
        int r = mb * 16 + ((lane >> 3) & 1) * 8 + (lane & 7);
        int cb = (lane >> 4) * 8;
        ldmx4(a_hi[0], smaddr(&hp_s[r][0  + cb]));
        ldmx4(a_hi[1], smaddr(&hp_s[r][16 + cb]));
        ldmx4(a_lo[0], smaddr(&hp_s[r][32 + cb]));
        ldmx4(a_lo[1], smaddr(&hp_s[r][48 + cb]));
    }

    float yacc[4][4];
#pragma unroll
    for (int i = 0; i < 4; i++)
#pragma unroll
        for (int q = 0; q < 4; q++) yacc[i][q] = 0.f;
    float z0 = 0.f, z1 = 0.f;
    float bv0 = -INFINITY, bv1 = -INFINITY;
    int   bk0 = 0, bk1 = 0;

    const int sb_row = nh * 64 + (lane & 7);
    const int sb_col = ((lane >> 3) & 1) * 8 + (lane >> 4) * 16;
    const int ab_rofs = nh * 64 + ((lane >> 3) & 1) * 8 + (lane & 7);
    const int ab_c8   = (lane >> 4) * 8;

    for (int ci = 0; ci < 16; ci++) {
        const int cur = ci & 1;
        const int c = cbase + ci;
        if (ci + 1 < 16) {
            int nb = 1 - cur;
            const char* src = (const char*)g_ehl + (size_t)(c + 1) * 128 * 128;
#pragma unroll
            for (int j = 0; j < 4; j++) {
                int i = tid + j * 256, r = i >> 3, c8 = i & 7;
                cpa16(smaddr(&e_s[nb][r][c8 * 8]), src + ((size_t)r * 64 + c8 * 8) * 2);
            }
            CP_COMMIT();
            CP_WAIT(1);
        } else {
            CP_WAIT(0);
        }
        __syncthreads();

        // ---- score pass ----
        uint32_t pk[8][2];
#pragma unroll
        for (int j = 0; j < 8; j++) {
            float s[4] = {0.f, 0.f, 0.f, 0.f};
            uint32_t bh[4], bl[4];
            uint32_t ad = smaddr(&e_s[cur][sb_row + j * 8][sb_col]);
            ldmx4(bh, ad);
            ldmx4(bl, ad + 64);
            mmaf16(s, a_hi[0], bh + 0); mmaf16(s, a_hi[1], bh + 2);
            mmaf16(s, a_lo[0], bh + 0); mmaf16(s, a_lo[1], bh + 2);
            mmaf16(s, a_hi[0], bl + 0); mmaf16(s, a_hi[1], bl + 2);

            int code0 = c * 128 + nh * 64 + j * 8 + t4 * 2;
            if (s[0] > bv0) { bv0 = s[0]; bk0 = code0; }
            if (s[1] > bv0) { bv0 = s[1]; bk0 = code0 + 1; }
            if (s[2] > bv1) { bv1 = s[2]; bk1 = code0; }
            if (s[3] > bv1) { bv1 = s[3]; bk1 = code0 + 1; }
            float p0 = ex2f(fmaf(s[0], 2.885390082f, -2.885390082f));
            float p1 = ex2f(fmaf(s[1], 2.885390082f, -2.885390082f));
            float p2 = ex2f(fmaf(s[2], 2.885390082f, -2.885390082f));
            float p3 = ex2f(fmaf(s[3], 2.885390082f, -2.885390082f));
            z0 += p0 + p1; z1 += p2 + p3;
            pk[j][0] = packh2(p0, p1);
            pk[j][1] = packh2(p2, p3);
        }

        // ---- accumulate pass: y += P @ E_hi (E_lo dropped, ~1e-4 rel) ----
#pragma unroll
        for (int kc = 0; kc < 4; kc++) {
            uint32_t A[4] = {pk[2*kc][0], pk[2*kc][1], pk[2*kc+1][0], pk[2*kc+1][1]};
            int crow = ab_rofs + kc * 16;
#pragma unroll
            for (int vtp = 0; vtp < 2; vtp++) {
                uint32_t bh[4];
                uint32_t ad = smaddr(&e_s[cur][crow][vtp * 16 + ab_c8]);
                ldmx4t(bh, ad);
                mmaf16(yacc[vtp*2+0], A, bh + 0); mmaf16(yacc[vtp*2+1], A, bh + 2);
            }
        }
        __syncthreads();
    }

    // ---- quad reductions ----
    z0 += __shfl_xor_sync(0xffffffffu, z0, 1); z0 += __shfl_xor_sync(0xffffffffu, z0, 2);
    z1 += __shfl_xor_sync(0xffffffffu, z1, 1); z1 += __shfl_xor_sync(0xffffffffu, z1, 2);
#pragma unroll
    for (int o = 1; o <= 2; o <<= 1) {
        float ob = __shfl_xor_sync(0xffffffffu, bv0, o);
        int   ok = __shfl_xor_sync(0xffffffffu, bk0, o);
        if (ob > bv0 || (ob == bv0 && ok < bk0)) { bv0 = ob; bk0 = ok; }
        ob = __shfl_xor_sync(0xffffffffu, bv1, o);
        ok = __shfl_xor_sync(0xffffffffu, bk1, o);
        if (ob > bv1 || (ob == bv1 && ok < bk1)) { bv1 = ob; bk1 = ok; }
    }

    int r0 = mb * 16 + g, r1 = r0 + 8;
    if (nh == 1) {
        if (t4 == 0) {
            epi->zs[r0] = z0; epi->bvs[r0] = bv0; epi->bks[r0] = bk0;
            epi->zs[r1] = z1; epi->bvs[r1] = bv1; epi->bks[r1] = bk1;
        }
#pragma unroll
        for (int vt = 0; vt < 4; vt++) {
            int cc = vt * 8 + t4 * 2;
            epi->ys[r0][cc] = yacc[vt][0]; epi->ys[r0][cc + 1] = yacc[vt][1];
            epi->ys[r1][cc] = yacc[vt][2]; epi->ys[r1][cc + 1] = yacc[vt][3];
        }
    }
    __syncthreads();
    if (nh == 0) {
        float Z0 = z0 + epi->zs[r0], Z1 = z1 + epi->zs[r1];
        {
            float ob = epi->bvs[r0]; int ok = epi->bks[r0];
            if (ob > bv0 || (ob == bv0 && ok < bk0)) { bv0 = ob; bk0 = ok; }
            ob = epi->bvs[r1]; ok = epi->bks[r1];
            if (ob > bv1 || (ob == bv1 && ok < bk1)) { bv1 = ob; bk1 = ok; }
        }
        int tok0 = t0 + r0, tok1 = t0 + r1;
        size_t base = (size_t)ks * NTOK;
#pragma unroll
        for (int vt = 0; vt < 4; vt++) {
            int cc = vt * 8 + t4 * 2;
            g_py[(base + tok0) * VD + cc]     = yacc[vt][0] + epi->ys[r0][cc];
            g_py[(base + tok0) * VD + cc + 1] = yacc[vt][1] + epi->ys[r0][cc + 1];
            g_py[(base + tok1) * VD + cc]     = yacc[vt][2] + epi->ys[r1][cc];
            g_py[(base + tok1) * VD + cc + 1] = yacc[vt][3] + epi->ys[r1][cc + 1];
        }
        if (t4 == 0) {
            g_pz[base + tok0] = Z0;  g_pz[base + tok1] = Z1;
            g_pbv[base + tok0] = bv0; g_pbv[base + tok1] = bv1;
            g_pbk[base + tok0] = bk0; g_pbk[base + tok1] = bk1;
        }
    }
}

// ---------------- Kernel D: merge partials + out = hvq @ Wpi^T + bpi (tensor) --------
// grid 256, block 256. CTA: 32 tokens x all 1024 d (8 chunks of 128 d rows).
// warp = (mb = wid>>2: 16-tok band) x (nq = wid&3: 32 d of each 128-chunk).
__global__ void __launch_bounds__(256, 2) k_out(const float* __restrict__ bpi,
                                                const float* __restrict__ attn_mask,
                                                float* __restrict__ out) {
    __shared__ __align__(16) __half eb[2][128][72];  // Wpi chunk [d][hi|lo]
    __shared__ __align__(16) __half ah[32][72];      // hvq [tok][hi 0:32 | lo 32:64]

    const int tid = threadIdx.x, wid = tid >> 5, lane = tid & 31;
    const int t0 = blockIdx.x * 32;
    const int mb = wid >> 2, nq = wid & 3;
    const int g = lane >> 2, t4 = lane & 3;

    // prefetch Wpi chunk 0
#pragma unroll
    for (int j = 0; j < 4; j++) {
        int i = tid + j * 256, r = i >> 3, c8 = i & 7;
        cpa16(smaddr(&eb[0][r][c8 * 8]), g_wpihl + (size_t)r * 64 + c8 * 8);
    }
    CP_COMMIT();

    // merge partials -> hvq -> hi/lo smem
    {
        int r = tid >> 3, c4 = (tid & 7) * 4;
        int tok = t0 + r;
        float4 y0 = *(const float4*)&g_py[(size_t)tok * VD + c4];
        float4 y1 = *(const float4*)&g_py[(size_t)(NTOK + tok) * VD + c4];
        float Z = g_pz[tok] + g_pz[NTOK + tok];
        float inv = (attn_mask[tok] == 1.0f) ? 1.0f / Z : 0.0f;
        float v0 = (y0.x + y1.x) * inv, v1 = (y0.y + y1.y) * inv;
        float v2 = (y0.z + y1.z) * inv, v3 = (y0.w + y1.w) * inv;
        __half h0, l0, h1, l1, h2, l2, h3, l3;
        hsplit(v0, h0, l0); hsplit(v1, h1, l1);
        hsplit(v2, h2, l2); hsplit(v3, h3, l3);
        __half hh[4] = {h0, h1, h2, h3};
        __half ll[4] = {l0, l1, l2, l3};
        *(uint2*)&ah[r][c4]      = *(uint2*)hh;
        *(uint2*)&ah[r][32 + c4] = *(uint2*)ll;
    }
    __syncthreads();

    uint32_t a_hi[2][4], a_lo[2][4];
    {
        int r = mb * 16 + ((lane >> 3) & 1) * 8 + (lane & 7);
        int cb = (lane >> 4) * 8;
        ldmx4(a_hi[0], smaddr(&ah[r][0  + cb]));
        ldmx4(a_hi[1], smaddr(&ah[r][16 + cb]));
        ldmx4(a_lo[0], smaddr(&ah[r][32 + cb]));
        ldmx4(a_lo[1], smaddr(&ah[r][48 + cb]));
    }

    const int sb_row = nq * 32 + (lane & 7);
    const int sb_col = ((lane >> 3) & 1) * 8 + (lane >> 4) * 16;

    for (int ci = 0; ci < 8; ci++) {
        const int cur = ci & 1;
        if (ci + 1 < 8) {
            int nb = 1 - cur;
            const __half* src = g_wpihl + (size_t)(ci + 1) * 128 * 64;
#pragma unroll
            for (int j = 0; j < 4; j++) {
                int i = tid + j * 256, r = i >> 3, c8 = i & 7;
                cpa16(smaddr(&eb[nb][r][c8 * 8]), src + (size_t)r * 64 + c8 * 8);
            }
            CP_COMMIT();
            CP_WAIT(1);
        } else {
            CP_WAIT(0);
        }
        __syncthreads();

#pragma unroll
        for (int j = 0; j < 4; j++) {
            float c[4] = {0.f, 0.f, 0.f, 0.f};
            uint32_t bh[4], bl[4];
            uint32_t ad = smaddr(&eb[cur][sb_row + j * 8][sb_col]);
            ldmx4(bh, ad);
            ldmx4(bl, ad + 64);
            mmaf16(c, a_hi[0], bh + 0); mmaf16(c, a_hi[1], bh + 2);
            mmaf16(c, a_lo[0], bh + 0); mmaf16(c, a_lo[1], bh + 2);
            mmaf16(c, a_hi[0], bl + 0); mmaf16(c, a_hi[1], bl + 2);

            int d = ci * 128 + nq * 32 + j * 8 + t4 * 2;
            float b0 = __ldg(&bpi[d]), b1 = __ldg(&bpi[d + 1]);
            int r0 = t0 + mb * 16 + g;
            float2 o0 = {c[0] + b0, c[1] + b1};
            float2 o1 = {c[2] + b0, c[3] + b1};
            *(float2*)&out[(size_t)r0 * DIM + d]       = o0;
            *(float2*)&out[(size_t)(r0 + 8) * DIM + d] = o1;
        }
        __syncthreads();
    }
}

// ---------------- Kernel E: tail (merge argmax, codes as float + loss) ----------------
__global__ void k_tail(const float* __restrict__ attn_mask,
                       float* __restrict__ out, int write_loss) {
    int i = blockIdx.x * blockDim.x + threadIdx.x;
    if (i < NTOK) {
        float bv0 = g_pbv[i], bv1 = g_pbv[NTOK + i];
        int   bk0 = g_pbk[i], bk1 = g_pbk[NTOK + i];
        int code = (bv1 > bv0) ? bk1 : bk0;
        float mk = attn_mask[i];
        out[(size_t)NTOK * DIM + i] = (mk == 1.0f) ? (float)code : 0.0f;
    }
    if (i == 0 && write_loss) out[(size_t)NTOK * DIM + NTOK] = 0.0f;
}

// ---------------- launch ----------------
extern "C" void kernel_launch(void* const* d_in, const int* in_sizes, int n_in,
                              void* d_out, int out_size) {
    const float* h    = (const float*)d_in[0];
    const float* mask = (const float*)d_in[1];
    const float* Wp   = (const float*)d_in[2];
    const float* bp   = (const float*)d_in[3];
    const float* Wpi  = (const float*)d_in[4];
    const float* bpi  = (const float*)d_in[5];
    const float* emb  = (const float*)d_in[6];
    float* out = (float*)d_out;

    k_embnorm<<<512, 256>>>(emb);
    k_wprep<<<128, 256>>>(Wp, Wpi);
    k_proj<<<256, 256>>>(h, bp);
    k_vq<<<256, 256>>>();
    k_out<<<256, 256>>>(bpi, mask, out);

    long long need = (long long)NTOK * DIM;
    if ((long long)out_size >= need + NTOK) {
        int wl = ((long long)out_size >= need + NTOK + 1) ? 1 : 0;
        k_tail<<<(NTOK + 255) / 256, 256>>>(mask, out, wl);
    }
}